// round 3
// baseline (speedup 1.0000x reference)
#include <cuda_runtime.h>
#include <math.h>

#define NROW 8192
#define DIN  512
#define DH   256
#define SLOPE 0.1f
#define CHUNK 64
#define NCHUNK 128   // NROW / CHUNK

// ---------------- scratch (device globals: no allocation allowed) ----------------
__device__ float    g_h[NROW * DH];                 // 8 MB
__device__ float    g_s1[NROW], g_s2[NROW];
__device__ unsigned g_s2max_u;
__device__ float    g_pj[NROW], g_qj[NROW];         // original order
__device__ float    g_s2s[NROW];                    // sorted s2
__device__ int      g_perm[NROW];                   // sorted -> original
__device__ float    g_ps[NROW], g_qs[NROW];         // sorted order
__device__ double   g_chP[NCHUNK * DH], g_chQ[NCHUNK * DH];
__device__ double   g_chSp[NCHUNK], g_chSq[NCHUNK];
__device__ double   g_TotP[DH];
__device__ double   g_SpTot;
__device__ float    g_SufP[(NROW + 1) * DH];        // fp32 suffix of p*h (sorted)
__device__ float    g_PreQ[(NROW + 1) * DH];        // fp32 prefix of q*h (sorted)
__device__ double   g_SpSuf[NROW + 1], g_SqPre[NROW + 1];
__device__ float    g_rowA[NROW], g_rowB[NROW], g_rowT[NROW];

// ordered-uint encoding of float for atomicMax
__device__ __forceinline__ unsigned f2ord(float x) {
    unsigned u = __float_as_uint(x);
    return (u & 0x80000000u) ? ~u : (u | 0x80000000u);
}
__device__ __forceinline__ float ord2f(unsigned u) {
    unsigned b = (u & 0x80000000u) ? (u & 0x7FFFFFFFu) : ~u;
    return __uint_as_float(b);
}

// ---------------- K1: h = doc @ W + W_b  (fp32 SGEMM 64x64x16, 512 CTAs) ----------------
__global__ __launch_bounds__(256) void k_gemm(const float* __restrict__ doc,
                                              const float* __restrict__ W,
                                              const float* __restrict__ Wb) {
    if (blockIdx.x == 0 && blockIdx.y == 0 && threadIdx.x == 0)
        g_s2max_u = 0u;   // reset ordered-max accumulator every call
    __shared__ float As[64][16];   // [m][k] — f4 stores conflict-free, broadcast reads
    __shared__ float Bs[16][64];   // [k][n]
    const int bm = blockIdx.x * 64;
    const int bn = blockIdx.y * 64;
    const int tid = threadIdx.x;
    const int ar = tid >> 2, ac4 = (tid & 3) << 2;    // doc 64x16 tile
    const int br = tid >> 4, bc4 = (tid & 15) << 2;   // W   16x64 tile
    const int tr = tid >> 4, tc = tid & 15;
    float acc[4][4];
#pragma unroll
    for (int i = 0; i < 4; i++)
#pragma unroll
        for (int j = 0; j < 4; j++) acc[i][j] = 0.f;

    for (int k0 = 0; k0 < DIN; k0 += 16) {
        float4 v = *(const float4*)&doc[(size_t)(bm + ar) * DIN + k0 + ac4];
        *(float4*)&As[ar][ac4] = v;
        float4 w = *(const float4*)&W[(size_t)(k0 + br) * DH + bn + bc4];
        *(float4*)&Bs[br][bc4] = w;
        __syncthreads();
#pragma unroll
        for (int kk = 0; kk < 16; kk++) {
            float a0 = As[tr * 4 + 0][kk];
            float a1 = As[tr * 4 + 1][kk];
            float a2 = As[tr * 4 + 2][kk];
            float a3 = As[tr * 4 + 3][kk];
            float4 b = *(float4*)&Bs[kk][tc * 4];
            acc[0][0] += a0 * b.x; acc[0][1] += a0 * b.y; acc[0][2] += a0 * b.z; acc[0][3] += a0 * b.w;
            acc[1][0] += a1 * b.x; acc[1][1] += a1 * b.y; acc[1][2] += a1 * b.z; acc[1][3] += a1 * b.w;
            acc[2][0] += a2 * b.x; acc[2][1] += a2 * b.y; acc[2][2] += a2 * b.z; acc[2][3] += a2 * b.w;
            acc[3][0] += a3 * b.x; acc[3][1] += a3 * b.y; acc[3][2] += a3 * b.z; acc[3][3] += a3 * b.w;
        }
        __syncthreads();
    }
    float4 wb = *(const float4*)&Wb[bn + tc * 4];
#pragma unroll
    for (int i = 0; i < 4; i++) {
        int r = bm + tr * 4 + i;
        float4 o;
        o.x = acc[i][0] + wb.x;
        o.y = acc[i][1] + wb.y;
        o.z = acc[i][2] + wb.z;
        o.w = acc[i][3] + wb.w;
        *(float4*)&g_h[(size_t)r * DH + bn + tc * 4] = o;
    }
}

// ---------------- K2: s1 = h@a1, s2 = h@a2 (warp/row) + global max(s2) ----------------
__global__ void k_s(const float* __restrict__ a) {
    __shared__ float smax[8];
    int wid = threadIdx.x >> 5;
    int lane = threadIdx.x & 31;
    int row = blockIdx.x * 8 + wid;
    const float* hr = &g_h[(size_t)row * DH];
    float s1 = 0.f, s2 = 0.f;
#pragma unroll
    for (int u = 0; u < 8; u++) {
        int c = u * 32 + lane;
        float hv = hr[c];
        s1 += hv * __ldg(&a[c]);
        s2 += hv * __ldg(&a[c + DH]);
    }
#pragma unroll
    for (int o = 16; o > 0; o >>= 1) {
        s1 += __shfl_xor_sync(0xffffffffu, s1, o);
        s2 += __shfl_xor_sync(0xffffffffu, s2, o);
    }
    if (lane == 0) { g_s1[row] = s1; g_s2[row] = s2; smax[wid] = s2; }
    __syncthreads();
    if (threadIdx.x == 0) {
        float m = smax[0];
#pragma unroll
        for (int u = 1; u < 8; u++) m = fmaxf(m, smax[u]);
        atomicMax(&g_s2max_u, f2ord(m));
    }
}

// ---------------- K3: fused rank+scatter (whole s2 in smem, no atomics) ----------------
__global__ __launch_bounds__(256) void k_rank() {
    __shared__ float s[NROW];   // 32 KB
    int tid = threadIdx.x;
    for (int i = tid; i < NROW; i += 256) s[i] = g_s2[i];
    __syncthreads();
    int j = blockIdx.x * 256 + tid;
    float v = s[j];
    int r = 0, e = 0;
    const float4* s4 = (const float4*)s;
#pragma unroll 4
    for (int u4 = 0; u4 < NROW / 4; u4++) {
        float4 w = s4[u4];
        r += (int)(w.x < v) + (int)(w.y < v) + (int)(w.z < v) + (int)(w.w < v);
        e += (int)(w.x == v) + (int)(w.y == v) + (int)(w.z == v) + (int)(w.w == v);
    }
    if (e > 1) {                       // rare duplicate: break ties by index
        int extra = 0;
        for (int u = 0; u < j; u++) extra += (int)(s[u] == v);
        r += extra;
    }
    float s2m = ord2f(g_s2max_u);
    float p = expf(v - s2m);
    float q = expf(SLOPE * (v - s2m));
    g_pj[j] = p; g_qj[j] = q;
    g_s2s[r] = v; g_perm[r] = j;
    g_ps[r] = p;  g_qs[r] = q;
}

// ---------------- K4: per-chunk fp64 sums of p*h, q*h (sorted order) ----------------
__global__ void k_chunk() {
    int cc = blockIdx.x;
    int c = threadIdx.x;
    __shared__ int   sperm[CHUNK];
    __shared__ float sp[CHUNK], sq[CHUNK];
    if (c < CHUNK) {
        int m = cc * CHUNK + c;
        sperm[c] = g_perm[m];
        sp[c] = g_ps[m];
        sq[c] = g_qs[m];
    }
    __syncthreads();
    double ap = 0.0, aq = 0.0;
#pragma unroll 4
    for (int u = 0; u < CHUNK; u++) {
        float hv = g_h[(size_t)sperm[u] * DH + c];
        ap += (double)sp[u] * (double)hv;
        aq += (double)sq[u] * (double)hv;
    }
    g_chP[cc * DH + c] = ap;
    g_chQ[cc * DH + c] = aq;
    if (c == 0) {
        double a = 0.0, b = 0.0;
        for (int u = 0; u < CHUNK; u++) { a += (double)sp[u]; b += (double)sq[u]; }
        g_chSp[cc] = a; g_chSq[cc] = b;
    }
}

// ---------------- K5: Kogge-Stone scan of chunk sums (block per column) ----------------
__global__ void k_scan() {
    __shared__ double sh[NCHUNK];
    int b = blockIdx.x;   // [0,256)=P col, [256,512)=Q col, 512=chSp, 513=chSq
    int t = threadIdx.x;
    double val;
    if (b < DH)            val = g_chP[t * DH + b];
    else if (b < 2 * DH)   val = g_chQ[t * DH + (b - DH)];
    else if (b == 2 * DH)  val = g_chSp[t];
    else                   val = g_chSq[t];
    sh[t] = val;
    __syncthreads();
#pragma unroll
    for (int off = 1; off < NCHUNK; off <<= 1) {
        double x = (t >= off) ? sh[t - off] : 0.0;
        __syncthreads();
        sh[t] += x;
        __syncthreads();
    }
    double excl = (t == 0) ? 0.0 : sh[t - 1];
    if (b < DH) {
        g_chP[t * DH + b] = excl;
        if (t == 0) g_TotP[b] = sh[NCHUNK - 1];
    } else if (b < 2 * DH) {
        g_chQ[t * DH + (b - DH)] = excl;
    } else if (b == 2 * DH) {
        g_chSp[t] = excl;
        if (t == 0) g_SpTot = sh[NCHUNK - 1];
    } else {
        g_chSq[t] = excl;
    }
}

// ---------------- K6: fp32 suffix/prefix arrays (fp64 accumulation) ----------------
__global__ void k_prefix() {
    int cc = blockIdx.x;
    int c = threadIdx.x;
    __shared__ int   sperm[CHUNK];
    __shared__ float sp[CHUNK], sq[CHUNK];
    if (c < CHUNK) {
        int m = cc * CHUNK + c;
        sperm[c] = g_perm[m];
        sp[c] = g_ps[m];
        sq[c] = g_qs[m];
    }
    __syncthreads();
    double rp = g_chP[cc * DH + c];
    double rq = g_chQ[cc * DH + c];
    double tot = g_TotP[c];
#pragma unroll 4
    for (int u = 0; u < CHUNK; u++) {
        int m = cc * CHUNK + u;
        g_SufP[(size_t)m * DH + c] = (float)(tot - rp);
        g_PreQ[(size_t)m * DH + c] = (float)rq;
        float hv = g_h[(size_t)sperm[u] * DH + c];
        rp += (double)sp[u] * (double)hv;
        rq += (double)sq[u] * (double)hv;
    }
    if (cc == NCHUNK - 1) {
        g_SufP[(size_t)NROW * DH + c] = (float)(tot - rp);
        g_PreQ[(size_t)NROW * DH + c] = (float)rq;
    }
    if (c == 0) {
        double ap = g_chSp[cc], aq = g_chSq[cc];
        double stot = g_SpTot;
        for (int u = 0; u < CHUNK; u++) {
            int m = cc * CHUNK + u;
            g_SpSuf[m] = stot - ap;
            g_SqPre[m] = aq;
            ap += (double)sp[u];
            aq += (double)sq[u];
        }
        if (cc == NCHUNK - 1) { g_SpSuf[NROW] = stot - ap; g_SqPre[NROW] = aq; }
    }
}

// ---------------- K7: out rows + per-row att coefficients ----------------
__global__ void k_out(const float* __restrict__ a_b, float* __restrict__ out) {
    int i = blockIdx.x;
    int c = threadIdx.x;
    __shared__ float sA, sB;
    __shared__ int sK;
    if (c == 0) {
        float cb = a_b[0];
        float s1 = g_s1[i];
        float s2m = ord2f(g_s2max_u);
        float u = s1 + cb + s2m;
        float m = u > 0.f ? u : SLOPE * u;          // exact row max of f(x)
        float alpha = expf(u - m);
        float beta  = expf(SLOPE * u - m);
        float t = -(s1 + cb);                       // x>0  <=>  s2[j] > t
        int lo = 0, hi = NROW;
        while (lo < hi) {
            int mid = (lo + hi) >> 1;
            if (g_s2s[mid] > t) hi = mid; else lo = mid + 1;
        }
        int k = lo;
        double Z = (double)alpha * g_SpSuf[k] + (double)beta * g_SqPre[k];
        float A = (float)((double)alpha / Z);
        float B = (float)((double)beta / Z);
        sA = A; sB = B; sK = k;
        g_rowA[i] = A; g_rowB[i] = B; g_rowT[i] = t;
    }
    __syncthreads();
    int k = sK;
    float v = sA * g_SufP[(size_t)k * DH + c] + sB * g_PreQ[(size_t)k * DH + c];
    out[(size_t)i * DH + c] = v > 0.f ? v : SLOPE * v;
}

// ---------------- K8: materialize att (268 MB; streaming stores) ----------------
__global__ void k_att(float* __restrict__ att) {
    int j = blockIdx.x * 1024 + threadIdx.x * 4;
    int i0 = blockIdx.y * 32;
    float4 p = *(const float4*)&g_pj[j];
    float4 q = *(const float4*)&g_qj[j];
    float4 s = *(const float4*)&g_s2[j];
#pragma unroll 4
    for (int r = 0; r < 32; r++) {
        int i = i0 + r;
        float A = __ldg(&g_rowA[i]);
        float B = __ldg(&g_rowB[i]);
        float T = __ldg(&g_rowT[i]);
        float4 o;
        o.x = s.x > T ? A * p.x : B * q.x;
        o.y = s.y > T ? A * p.y : B * q.y;
        o.z = s.z > T ? A * p.z : B * q.z;
        o.w = s.w > T ? A * p.w : B * q.w;
        __stcs((float4*)&att[(size_t)i * NROW + j], o);
    }
}

// ---------------- launch ----------------
extern "C" void kernel_launch(void* const* d_in, const int* in_sizes, int n_in,
                              void* d_out, int out_size) {
    const float* doc = (const float*)d_in[0];
    const float* W   = (const float*)d_in[1];
    const float* Wb  = (const float*)d_in[2];
    const float* a   = (const float*)d_in[3];
    const float* ab  = (const float*)d_in[4];
    float* out = (float*)d_out;                  // [8192 x 256]
    float* att = out + (size_t)NROW * DH;        // [8192 x 8192]

    k_gemm<<<dim3(NROW / 64, DH / 64), 256>>>(doc, W, Wb);
    k_s<<<NROW / 8, 256>>>(a);
    k_rank<<<NROW / 256, 256>>>();
    k_chunk<<<NCHUNK, 256>>>();
    k_scan<<<2 * DH + 2, NCHUNK>>>();
    k_prefix<<<NCHUNK, 256>>>();
    k_out<<<NROW, 256>>>(ab, out);
    k_att<<<dim3(NROW / 1024, NROW / 32), 256>>>(att);
}

// round 4
// speedup vs baseline: 1.5710x; 1.5710x over previous
#include <cuda_runtime.h>
#include <math.h>

#define NROW 8192
#define DIN  512
#define DH   256
#define SLOPE 0.1f
#define CHUNK 64
#define NCHUNK 128   // NROW / CHUNK

// ---------------- scratch (device globals: no allocation allowed) ----------------
__device__ float    g_h[NROW * DH];                 // 8 MB
__device__ float    g_s1[NROW], g_s2[NROW];
__device__ unsigned g_s2max_u;
__device__ int      g_rank[NROW];
__device__ float    g_pj[NROW], g_qj[NROW];         // original order
__device__ float    g_s2s[NROW];                    // sorted s2
__device__ int      g_perm[NROW];                   // sorted -> original
__device__ float    g_ps[NROW], g_qs[NROW];         // sorted order
__device__ double   g_chP[NCHUNK * DH], g_chQ[NCHUNK * DH];
__device__ double   g_chSp[NCHUNK], g_chSq[NCHUNK];
__device__ double   g_TotP[DH];
__device__ double   g_SpTot;
__device__ float    g_SufP[(NROW + 1) * DH];        // fp32 suffix of p*h (sorted)
__device__ float    g_PreQ[(NROW + 1) * DH];        // fp32 prefix of q*h (sorted)
__device__ double   g_SpSuf[NROW + 1], g_SqPre[NROW + 1];
__device__ float    g_rowA[NROW], g_rowB[NROW], g_rowT[NROW];

// ordered-uint encoding of float for atomicMax
__device__ __forceinline__ unsigned f2ord(float x) {
    unsigned u = __float_as_uint(x);
    return (u & 0x80000000u) ? ~u : (u | 0x80000000u);
}
__device__ __forceinline__ float ord2f(unsigned u) {
    unsigned b = (u & 0x80000000u) ? (u & 0x7FFFFFFFu) : ~u;
    return __uint_as_float(b);
}

// packed f32x2 helpers (sm_100a: fma.rn.f32x2 — ptxas never emits it, PTX only)
__device__ __forceinline__ unsigned long long pack2(float v) {
    unsigned long long r;
    asm("mov.b64 %0, {%1, %1};" : "=l"(r) : "r"(__float_as_uint(v)));
    return r;
}
__device__ __forceinline__ unsigned long long fma2(unsigned long long a,
                                                   unsigned long long b,
                                                   unsigned long long c) {
    unsigned long long d;
    asm("fma.rn.f32x2 %0, %1, %2, %3;" : "=l"(d) : "l"(a), "l"(b), "l"(c));
    return d;
}
__device__ __forceinline__ void unpack2(unsigned long long v, float& lo, float& hi) {
    unsigned a, b;
    asm("mov.b64 {%0, %1}, %2;" : "=r"(a), "=r"(b) : "l"(v));
    lo = __uint_as_float(a); hi = __uint_as_float(b);
}

// ---------------- K1: h = doc @ W + W_b (fp32x2 SGEMM 128x64x16, 256 CTAs) ----------------
__global__ __launch_bounds__(256, 2) void k_gemm(const float* __restrict__ doc,
                                                 const float* __restrict__ W,
                                                 const float* __restrict__ Wb) {
    if (blockIdx.x == 0 && blockIdx.y == 0 && threadIdx.x == 0)
        g_s2max_u = 0u;   // reset ordered-max accumulator every replay
    __shared__ float As[16][128];   // [k][m] — m contiguous for u64 pair loads
    __shared__ float Bs[16][64];    // [k][n]
    const int bm = blockIdx.x * 128;
    const int bn = blockIdx.y * 64;
    const int tid = threadIdx.x;
    const int tr = tid >> 4, tc = tid & 15;   // 16x16 threads; thread tile 8m x 4n
    unsigned long long acc[4][4];             // [m-pair][n], each = 2 fp32 (m even, m odd)
#pragma unroll
    for (int i = 0; i < 4; i++)
#pragma unroll
        for (int j = 0; j < 4; j++) acc[i][j] = 0ull;

    for (int k0 = 0; k0 < DIN; k0 += 16) {
        // A tile 128x16: 512 float4 loads, 2 per thread; store transposed [k][m]
#pragma unroll
        for (int l = 0; l < 2; l++) {
            int f = tid + l * 256;
            int ar = f >> 2, ac4 = (f & 3) << 2;
            float4 v = *(const float4*)&doc[(size_t)(bm + ar) * DIN + k0 + ac4];
            As[ac4 + 0][ar] = v.x; As[ac4 + 1][ar] = v.y;
            As[ac4 + 2][ar] = v.z; As[ac4 + 3][ar] = v.w;
        }
        // B tile 16x64: 256 float4, 1 per thread
        {
            int br = tid >> 4, bc4 = (tid & 15) << 2;
            float4 w = *(const float4*)&W[(size_t)(k0 + br) * DH + bn + bc4];
            *(float4*)&Bs[br][bc4] = w;
        }
        __syncthreads();
#pragma unroll
        for (int kk = 0; kk < 16; kk++) {
            ulonglong2 av0 = *(const ulonglong2*)&As[kk][tr * 8];
            ulonglong2 av1 = *(const ulonglong2*)&As[kk][tr * 8 + 4];
            unsigned long long a64[4] = {av0.x, av0.y, av1.x, av1.y};
            float4 bf = *(const float4*)&Bs[kk][tc * 4];
            unsigned long long bp[4] = {pack2(bf.x), pack2(bf.y), pack2(bf.z), pack2(bf.w)};
#pragma unroll
            for (int mp = 0; mp < 4; mp++)
#pragma unroll
                for (int n = 0; n < 4; n++)
                    acc[mp][n] = fma2(a64[mp], bp[n], acc[mp][n]);
        }
        __syncthreads();
    }
    float4 wb = *(const float4*)&Wb[bn + tc * 4];
#pragma unroll
    for (int mp = 0; mp < 4; mp++) {
        int m0 = bm + tr * 8 + 2 * mp;
        float lo0, hi0, lo1, hi1, lo2, hi2, lo3, hi3;
        unpack2(acc[mp][0], lo0, hi0);
        unpack2(acc[mp][1], lo1, hi1);
        unpack2(acc[mp][2], lo2, hi2);
        unpack2(acc[mp][3], lo3, hi3);
        float4 r0, r1;
        r0.x = lo0 + wb.x; r0.y = lo1 + wb.y; r0.z = lo2 + wb.z; r0.w = lo3 + wb.w;
        r1.x = hi0 + wb.x; r1.y = hi1 + wb.y; r1.z = hi2 + wb.z; r1.w = hi3 + wb.w;
        *(float4*)&g_h[(size_t)m0 * DH + bn + tc * 4] = r0;
        *(float4*)&g_h[(size_t)(m0 + 1) * DH + bn + tc * 4] = r1;
    }
}

// ---------------- K2: s1 = h@a1, s2 = h@a2 (warp/row) + global max + rank zero ----------------
__global__ void k_s(const float* __restrict__ a) {
    __shared__ float smax[8];
    int wid = threadIdx.x >> 5;
    int lane = threadIdx.x & 31;
    int row = blockIdx.x * 8 + wid;
    const float* hr = &g_h[(size_t)row * DH];
    float s1 = 0.f, s2 = 0.f;
#pragma unroll
    for (int u = 0; u < 8; u++) {
        int c = u * 32 + lane;
        float hv = hr[c];
        s1 += hv * __ldg(&a[c]);
        s2 += hv * __ldg(&a[c + DH]);
    }
#pragma unroll
    for (int o = 16; o > 0; o >>= 1) {
        s1 += __shfl_xor_sync(0xffffffffu, s1, o);
        s2 += __shfl_xor_sync(0xffffffffu, s2, o);
    }
    if (lane == 0) {
        g_s1[row] = s1; g_s2[row] = s2; g_rank[row] = 0; smax[wid] = s2;
    }
    __syncthreads();
    if (threadIdx.x == 0) {
        float m = smax[0];
#pragma unroll
        for (int u = 1; u < 8; u++) m = fmaxf(m, smax[u]);
        atomicMax(&g_s2max_u, f2ord(m));
    }
}

// ---------------- K3: partial rank counts (8-way split over comparand range) ----------------
__global__ void k_rank_part() {
    __shared__ float tile[256];
    int j = blockIdx.x * 256 + threadIdx.x;
    float v = g_s2[j];
    int base = blockIdx.y * 1024;
    int rank = 0;
    for (int t0 = base; t0 < base + 1024; t0 += 256) {
        tile[threadIdx.x] = g_s2[t0 + threadIdx.x];
        __syncthreads();
#pragma unroll 8
        for (int u = 0; u < 256; u++) {
            float w = tile[u];
            rank += (int)((w < v) || (w == v && (t0 + u) < j));
        }
        __syncthreads();
    }
    atomicAdd(&g_rank[j], rank);
}

// ---------------- K4: scatter into sorted order; compute p, q ----------------
__global__ void k_scatter() {
    int j = blockIdx.x * 256 + threadIdx.x;
    float v = g_s2[j];
    int r = g_rank[j];
    float s2m = ord2f(g_s2max_u);
    float p = expf(v - s2m);
    float q = expf(SLOPE * (v - s2m));
    g_pj[j] = p; g_qj[j] = q;
    g_s2s[r] = v; g_perm[r] = j;
    g_ps[r] = p;  g_qs[r] = q;
}

// ---------------- K5: per-chunk sums of p*h, q*h (fp32 accum, fp64 store) ----------------
__global__ void k_chunk() {
    int cc = blockIdx.x;
    int c = threadIdx.x;
    __shared__ int   sperm[CHUNK];
    __shared__ float sp[CHUNK], sq[CHUNK];
    __shared__ double red[CHUNK];
    if (c < CHUNK) {
        int m = cc * CHUNK + c;
        sperm[c] = g_perm[m];
        sp[c] = g_ps[m];
        sq[c] = g_qs[m];
    }
    __syncthreads();
    float ap0 = 0.f, ap1 = 0.f, aq0 = 0.f, aq1 = 0.f;
#pragma unroll 4
    for (int u = 0; u < CHUNK; u += 2) {
        float h0 = g_h[(size_t)sperm[u] * DH + c];
        float h1 = g_h[(size_t)sperm[u + 1] * DH + c];
        ap0 += sp[u] * h0;     aq0 += sq[u] * h0;
        ap1 += sp[u + 1] * h1; aq1 += sq[u + 1] * h1;
    }
    g_chP[cc * DH + c] = (double)(ap0 + ap1);
    g_chQ[cc * DH + c] = (double)(aq0 + aq1);
    // scalar chunk sums of p, q — parallel fp64 tree
    if (c < CHUNK) red[c] = (double)sp[c];
    __syncthreads();
    for (int o = CHUNK / 2; o > 0; o >>= 1) {
        if (c < o) red[c] += red[c + o];
        __syncthreads();
    }
    if (c == 0) g_chSp[cc] = red[0];
    __syncthreads();
    if (c < CHUNK) red[c] = (double)sq[c];
    __syncthreads();
    for (int o = CHUNK / 2; o > 0; o >>= 1) {
        if (c < o) red[c] += red[c + o];
        __syncthreads();
    }
    if (c == 0) g_chSq[cc] = red[0];
}

// ---------------- K6: Kogge-Stone scan of chunk sums (block per column) ----------------
__global__ void k_scan() {
    __shared__ double sh[NCHUNK];
    int b = blockIdx.x;   // [0,256)=P col, [256,512)=Q col, 512=chSp, 513=chSq
    int t = threadIdx.x;
    double val;
    if (b < DH)            val = g_chP[t * DH + b];
    else if (b < 2 * DH)   val = g_chQ[t * DH + (b - DH)];
    else if (b == 2 * DH)  val = g_chSp[t];
    else                   val = g_chSq[t];
    sh[t] = val;
    __syncthreads();
#pragma unroll
    for (int off = 1; off < NCHUNK; off <<= 1) {
        double x = (t >= off) ? sh[t - off] : 0.0;
        __syncthreads();
        sh[t] += x;
        __syncthreads();
    }
    double excl = (t == 0) ? 0.0 : sh[t - 1];
    if (b < DH) {
        g_chP[t * DH + b] = excl;
        if (t == 0) g_TotP[b] = sh[NCHUNK - 1];
    } else if (b < 2 * DH) {
        g_chQ[t * DH + (b - DH)] = excl;
    } else if (b == 2 * DH) {
        g_chSp[t] = excl;
        if (t == 0) g_SpTot = sh[NCHUNK - 1];
    } else {
        g_chSq[t] = excl;
    }
}

// ---------------- K7: fp32 suffix/prefix arrays (fp32 local accum off fp64 bases) ----------------
__global__ void k_prefix() {
    int cc = blockIdx.x;
    int c = threadIdx.x;
    __shared__ int   sperm[CHUNK];
    __shared__ float sp[CHUNK], sq[CHUNK];
    __shared__ double eP[CHUNK + 1], eQ[CHUNK + 1], ks[CHUNK];
    if (c < CHUNK) {
        int m = cc * CHUNK + c;
        sperm[c] = g_perm[m];
        sp[c] = g_ps[m];
        sq[c] = g_qs[m];
    }
    __syncthreads();
    // in-chunk scalar exclusive scans of sp, sq (Kogge-Stone, fp64, 64 wide)
    if (c < CHUNK) ks[c] = (double)sp[c];
    __syncthreads();
#pragma unroll
    for (int o = 1; o < CHUNK; o <<= 1) {
        double x = (c < CHUNK && c >= o) ? ks[c - o] : 0.0;
        __syncthreads();
        if (c < CHUNK) ks[c] += x;
        __syncthreads();
    }
    if (c < CHUNK) { eP[c + 1] = ks[c]; if (c == 0) eP[0] = 0.0; }
    __syncthreads();
    if (c < CHUNK) ks[c] = (double)sq[c];
    __syncthreads();
#pragma unroll
    for (int o = 1; o < CHUNK; o <<= 1) {
        double x = (c < CHUNK && c >= o) ? ks[c - o] : 0.0;
        __syncthreads();
        if (c < CHUNK) ks[c] += x;
        __syncthreads();
    }
    if (c < CHUNK) { eQ[c + 1] = ks[c]; if (c == 0) eQ[0] = 0.0; }
    __syncthreads();

    // per-column: fp32 running sums against fp32 bases (fp64 only once per block)
    double rp0 = g_chP[cc * DH + c];
    double rq0 = g_chQ[cc * DH + c];
    float sufBase = (float)(g_TotP[c] - rp0);
    float preBase = (float)rq0;
    float lp = 0.f, lq = 0.f;
#pragma unroll 4
    for (int u = 0; u < CHUNK; u++) {
        size_t m = (size_t)cc * CHUNK + u;
        g_SufP[m * DH + c] = sufBase - lp;
        g_PreQ[m * DH + c] = preBase + lq;
        float hv = g_h[(size_t)sperm[u] * DH + c];
        lp += sp[u] * hv;
        lq += sq[u] * hv;
    }
    if (cc == NCHUNK - 1) {
        g_SufP[(size_t)NROW * DH + c] = sufBase - lp;
        g_PreQ[(size_t)NROW * DH + c] = preBase + lq;
    }
    // scalar prefix arrays (fp64, parallel over 64 threads)
    if (c < CHUNK) {
        int m = cc * CHUNK + c;
        double bSp = g_chSp[cc], bSq = g_chSq[cc], stot = g_SpTot;
        g_SpSuf[m] = stot - (bSp + eP[c]);
        g_SqPre[m] = bSq + eQ[c];
        if (cc == NCHUNK - 1 && c == CHUNK - 1) {
            g_SpSuf[NROW] = stot - (bSp + eP[CHUNK]);
            g_SqPre[NROW] = bSq + eQ[CHUNK];
        }
    }
}

// ---------------- K8: out rows + per-row att coefficients ----------------
__global__ void k_out(const float* __restrict__ a_b, float* __restrict__ out) {
    int i = blockIdx.x;
    int c = threadIdx.x;
    __shared__ float sA, sB;
    __shared__ int sK;
    if (c == 0) {
        float cb = a_b[0];
        float s1 = g_s1[i];
        float s2m = ord2f(g_s2max_u);
        float u = s1 + cb + s2m;
        float m = u > 0.f ? u : SLOPE * u;          // exact row max of f(x)
        float alpha = expf(u - m);
        float beta  = expf(SLOPE * u - m);
        float t = -(s1 + cb);                       // x>0  <=>  s2[j] > t
        int lo = 0, hi = NROW;
        while (lo < hi) {
            int mid = (lo + hi) >> 1;
            if (g_s2s[mid] > t) hi = mid; else lo = mid + 1;
        }
        int k = lo;
        double Z = (double)alpha * g_SpSuf[k] + (double)beta * g_SqPre[k];
        float A = (float)((double)alpha / Z);
        float B = (float)((double)beta / Z);
        sA = A; sB = B; sK = k;
        g_rowA[i] = A; g_rowB[i] = B; g_rowT[i] = t;
    }
    __syncthreads();
    int k = sK;
    float v = sA * g_SufP[(size_t)k * DH + c] + sB * g_PreQ[(size_t)k * DH + c];
    out[(size_t)i * DH + c] = v > 0.f ? v : SLOPE * v;
}

// ---------------- K9: materialize att (268 MB; streaming stores) ----------------
__global__ void k_att(float* __restrict__ att) {
    int j = blockIdx.x * 1024 + threadIdx.x * 4;
    int i0 = blockIdx.y * 32;
    float4 p = *(const float4*)&g_pj[j];
    float4 q = *(const float4*)&g_qj[j];
    float4 s = *(const float4*)&g_s2[j];
#pragma unroll 4
    for (int r = 0; r < 32; r++) {
        int i = i0 + r;
        float A = __ldg(&g_rowA[i]);
        float B = __ldg(&g_rowB[i]);
        float T = __ldg(&g_rowT[i]);
        float4 o;
        o.x = s.x > T ? A * p.x : B * q.x;
        o.y = s.y > T ? A * p.y : B * q.y;
        o.z = s.z > T ? A * p.z : B * q.z;
        o.w = s.w > T ? A * p.w : B * q.w;
        __stcs((float4*)&att[(size_t)i * NROW + j], o);
    }
}

// ---------------- launch ----------------
extern "C" void kernel_launch(void* const* d_in, const int* in_sizes, int n_in,
                              void* d_out, int out_size) {
    const float* doc = (const float*)d_in[0];
    const float* W   = (const float*)d_in[1];
    const float* Wb  = (const float*)d_in[2];
    const float* a   = (const float*)d_in[3];
    const float* ab  = (const float*)d_in[4];
    float* out = (float*)d_out;                  // [8192 x 256]
    float* att = out + (size_t)NROW * DH;        // [8192 x 8192]

    k_gemm<<<dim3(NROW / 128, DH / 64), 256>>>(doc, W, Wb);
    k_s<<<NROW / 8, 256>>>(a);
    k_rank_part<<<dim3(32, 8), 256>>>();
    k_scatter<<<32, 256>>>();
    k_chunk<<<NCHUNK, 256>>>();
    k_scan<<<2 * DH + 2, NCHUNK>>>();
    k_prefix<<<NCHUNK, 256>>>();
    k_out<<<NROW, 256>>>(ab, out);
    k_att<<<dim3(NROW / 1024, NROW / 32), 256>>>(att);
}

// round 5
// speedup vs baseline: 1.7836x; 1.1353x over previous
#include <cuda_runtime.h>
#include <math.h>

#define NROW 8192
#define DIN  512
#define DH   256
#define SLOPE 0.1f
#define CHUNK 64
#define NCHUNK 128   // NROW / CHUNK

// ---------------- scratch (device globals: no allocation allowed) ----------------
__device__ float    g_h[NROW * DH];                 // 8 MB
__device__ float    g_s1[NROW], g_s2[NROW];
__device__ unsigned g_s2max_u;
__device__ int      g_rank[NROW];
__device__ float    g_pj[NROW], g_qj[NROW];         // original order
__device__ float    g_s2s[NROW];                    // sorted s2
__device__ int      g_perm[NROW];                   // sorted -> original
__device__ float    g_ps[NROW], g_qs[NROW];         // sorted order
__device__ double   g_chP[NCHUNK * DH], g_chQ[NCHUNK * DH];
__device__ double   g_chSp[NCHUNK], g_chSq[NCHUNK];
__device__ double   g_TotP[DH];
__device__ double   g_SpTot;
__device__ float    g_SufP[(NROW + 1) * DH];        // fp32 suffix of p*h (sorted)
__device__ float    g_PreQ[(NROW + 1) * DH];        // fp32 prefix of q*h (sorted)
__device__ double   g_SpSuf[NROW + 1], g_SqPre[NROW + 1];
__device__ float    g_rowA[NROW], g_rowB[NROW], g_rowT[NROW];
__device__ int      g_rowK[NROW];

// ordered-uint encoding of float for atomicMax
__device__ __forceinline__ unsigned f2ord(float x) {
    unsigned u = __float_as_uint(x);
    return (u & 0x80000000u) ? ~u : (u | 0x80000000u);
}
__device__ __forceinline__ float ord2f(unsigned u) {
    unsigned b = (u & 0x80000000u) ? (u & 0x7FFFFFFFu) : ~u;
    return __uint_as_float(b);
}

// packed f32x2 helpers (sm_100a: fma.rn.f32x2 — ptxas never emits it, PTX only)
__device__ __forceinline__ unsigned long long pack2(float v) {
    unsigned long long r;
    asm("mov.b64 %0, {%1, %1};" : "=l"(r) : "r"(__float_as_uint(v)));
    return r;
}
__device__ __forceinline__ unsigned long long fma2(unsigned long long a,
                                                   unsigned long long b,
                                                   unsigned long long c) {
    unsigned long long d;
    asm("fma.rn.f32x2 %0, %1, %2, %3;" : "=l"(d) : "l"(a), "l"(b), "l"(c));
    return d;
}
__device__ __forceinline__ void unpack2(unsigned long long v, float& lo, float& hi) {
    unsigned a, b;
    asm("mov.b64 {%0, %1}, %2;" : "=r"(a), "=r"(b) : "l"(v));
    lo = __uint_as_float(a); hi = __uint_as_float(b);
}

// ---------------- K1: h = doc @ W + W_b (fp32x2 SGEMM 128x64, double-buffered) ----------------
__global__ __launch_bounds__(256, 2) void k_gemm(const float* __restrict__ doc,
                                                 const float* __restrict__ W,
                                                 const float* __restrict__ Wb) {
    if (blockIdx.x == 0 && blockIdx.y == 0 && threadIdx.x == 0)
        g_s2max_u = 0u;   // reset ordered-max accumulator every replay
    __shared__ float As[2][16][128];   // [buf][k][m]
    __shared__ float Bs[2][16][64];    // [buf][k][n]
    const int bm = blockIdx.x * 128;
    const int bn = blockIdx.y * 64;
    const int tid = threadIdx.x;
    const int tr = tid >> 4, tc = tid & 15;   // thread tile 8m x 4n
    // loader indices
    const int ar0 = tid >> 2,          ac0 = (tid & 3) << 2;          // A part 0
    const int ar1 = (tid + 256) >> 2,  ac1 = ((tid + 256) & 3) << 2;  // A part 1
    const int br  = tid >> 4,          bc  = (tid & 15) << 2;         // B

    unsigned long long acc[4][4];
#pragma unroll
    for (int i = 0; i < 4; i++)
#pragma unroll
        for (int j = 0; j < 4; j++) acc[i][j] = 0ull;

    // prologue: load step 0 into buffer 0
    {
        float4 v0 = *(const float4*)&doc[(size_t)(bm + ar0) * DIN + ac0];
        float4 v1 = *(const float4*)&doc[(size_t)(bm + ar1) * DIN + ac1];
        float4 w  = *(const float4*)&W[(size_t)br * DH + bn + bc];
        As[0][ac0 + 0][ar0] = v0.x; As[0][ac0 + 1][ar0] = v0.y;
        As[0][ac0 + 2][ar0] = v0.z; As[0][ac0 + 3][ar0] = v0.w;
        As[0][ac1 + 0][ar1] = v1.x; As[0][ac1 + 1][ar1] = v1.y;
        As[0][ac1 + 2][ar1] = v1.z; As[0][ac1 + 3][ar1] = v1.w;
        *(float4*)&Bs[0][br][bc] = w;
    }
    __syncthreads();

    const int NSTEP = DIN / 16;   // 32
    for (int step = 0; step < NSTEP; step++) {
        int cur = step & 1;
        float4 v0, v1, w;
        if (step < NSTEP - 1) {
            int k0n = (step + 1) * 16;
            v0 = *(const float4*)&doc[(size_t)(bm + ar0) * DIN + k0n + ac0];
            v1 = *(const float4*)&doc[(size_t)(bm + ar1) * DIN + k0n + ac1];
            w  = *(const float4*)&W[(size_t)(k0n + br) * DH + bn + bc];
        }
#pragma unroll
        for (int kk = 0; kk < 16; kk++) {
            ulonglong2 av0 = *(const ulonglong2*)&As[cur][kk][tr * 8];
            ulonglong2 av1 = *(const ulonglong2*)&As[cur][kk][tr * 8 + 4];
            unsigned long long a64[4] = {av0.x, av0.y, av1.x, av1.y};
            float4 bf = *(const float4*)&Bs[cur][kk][tc * 4];
            unsigned long long bp[4] = {pack2(bf.x), pack2(bf.y), pack2(bf.z), pack2(bf.w)};
#pragma unroll
            for (int mp = 0; mp < 4; mp++)
#pragma unroll
                for (int n = 0; n < 4; n++)
                    acc[mp][n] = fma2(a64[mp], bp[n], acc[mp][n]);
        }
        if (step < NSTEP - 1) {
            int nxt = cur ^ 1;
            As[nxt][ac0 + 0][ar0] = v0.x; As[nxt][ac0 + 1][ar0] = v0.y;
            As[nxt][ac0 + 2][ar0] = v0.z; As[nxt][ac0 + 3][ar0] = v0.w;
            As[nxt][ac1 + 0][ar1] = v1.x; As[nxt][ac1 + 1][ar1] = v1.y;
            As[nxt][ac1 + 2][ar1] = v1.z; As[nxt][ac1 + 3][ar1] = v1.w;
            *(float4*)&Bs[nxt][br][bc] = w;
        }
        __syncthreads();
    }

    float4 wb = *(const float4*)&Wb[bn + tc * 4];
#pragma unroll
    for (int mp = 0; mp < 4; mp++) {
        int m0 = bm + tr * 8 + 2 * mp;
        float lo0, hi0, lo1, hi1, lo2, hi2, lo3, hi3;
        unpack2(acc[mp][0], lo0, hi0);
        unpack2(acc[mp][1], lo1, hi1);
        unpack2(acc[mp][2], lo2, hi2);
        unpack2(acc[mp][3], lo3, hi3);
        float4 r0, r1;
        r0.x = lo0 + wb.x; r0.y = lo1 + wb.y; r0.z = lo2 + wb.z; r0.w = lo3 + wb.w;
        r1.x = hi0 + wb.x; r1.y = hi1 + wb.y; r1.z = hi2 + wb.z; r1.w = hi3 + wb.w;
        *(float4*)&g_h[(size_t)m0 * DH + bn + tc * 4] = r0;
        *(float4*)&g_h[(size_t)(m0 + 1) * DH + bn + tc * 4] = r1;
    }
}

// ---------------- K2: s1 = h@a1, s2 = h@a2 (warp/row) + global max + rank zero ----------------
__global__ void k_s(const float* __restrict__ a) {
    __shared__ float smax[8];
    int wid = threadIdx.x >> 5;
    int lane = threadIdx.x & 31;
    int row = blockIdx.x * 8 + wid;
    const float* hr = &g_h[(size_t)row * DH];
    float s1 = 0.f, s2 = 0.f;
#pragma unroll
    for (int u = 0; u < 8; u++) {
        int c = u * 32 + lane;
        float hv = hr[c];
        s1 += hv * __ldg(&a[c]);
        s2 += hv * __ldg(&a[c + DH]);
    }
#pragma unroll
    for (int o = 16; o > 0; o >>= 1) {
        s1 += __shfl_xor_sync(0xffffffffu, s1, o);
        s2 += __shfl_xor_sync(0xffffffffu, s2, o);
    }
    if (lane == 0) {
        g_s1[row] = s1; g_s2[row] = s2; g_rank[row] = 0; smax[wid] = s2;
    }
    __syncthreads();
    if (threadIdx.x == 0) {
        float m = smax[0];
#pragma unroll
        for (int u = 1; u < 8; u++) m = fmaxf(m, smax[u]);
        atomicMax(&g_s2max_u, f2ord(m));
    }
}

// ---------------- K3: partial rank counts (8-way split over comparand range) ----------------
__global__ void k_rank_part() {
    __shared__ float tile[256];
    int j = blockIdx.x * 256 + threadIdx.x;
    float v = g_s2[j];
    int base = blockIdx.y * 1024;
    int rank = 0;
    for (int t0 = base; t0 < base + 1024; t0 += 256) {
        tile[threadIdx.x] = g_s2[t0 + threadIdx.x];
        __syncthreads();
#pragma unroll 8
        for (int u = 0; u < 256; u++) {
            float w = tile[u];
            rank += (int)((w < v) || (w == v && (t0 + u) < j));
        }
        __syncthreads();
    }
    atomicAdd(&g_rank[j], rank);
}

// ---------------- K4: scatter into sorted order; compute p, q ----------------
__global__ void k_scatter() {
    int j = blockIdx.x * 256 + threadIdx.x;
    float v = g_s2[j];
    int r = g_rank[j];
    float s2m = ord2f(g_s2max_u);
    float p = expf(v - s2m);
    float q = expf(SLOPE * (v - s2m));
    g_pj[j] = p; g_qj[j] = q;
    g_s2s[r] = v; g_perm[r] = j;
    g_ps[r] = p;  g_qs[r] = q;
}

// ---------------- K5: per-chunk sums of p*h, q*h (fp32 accum, fp64 store) ----------------
__global__ void k_chunk() {
    int cc = blockIdx.x;
    int c = threadIdx.x;
    __shared__ int   sperm[CHUNK];
    __shared__ float sp[CHUNK], sq[CHUNK];
    __shared__ double red[CHUNK];
    if (c < CHUNK) {
        int m = cc * CHUNK + c;
        sperm[c] = g_perm[m];
        sp[c] = g_ps[m];
        sq[c] = g_qs[m];
    }
    __syncthreads();
    float ap0 = 0.f, ap1 = 0.f, aq0 = 0.f, aq1 = 0.f;
#pragma unroll 4
    for (int u = 0; u < CHUNK; u += 2) {
        float h0 = g_h[(size_t)sperm[u] * DH + c];
        float h1 = g_h[(size_t)sperm[u + 1] * DH + c];
        ap0 += sp[u] * h0;     aq0 += sq[u] * h0;
        ap1 += sp[u + 1] * h1; aq1 += sq[u + 1] * h1;
    }
    g_chP[cc * DH + c] = (double)(ap0 + ap1);
    g_chQ[cc * DH + c] = (double)(aq0 + aq1);
    if (c < CHUNK) red[c] = (double)sp[c];
    __syncthreads();
    for (int o = CHUNK / 2; o > 0; o >>= 1) {
        if (c < o) red[c] += red[c + o];
        __syncthreads();
    }
    if (c == 0) g_chSp[cc] = red[0];
    __syncthreads();
    if (c < CHUNK) red[c] = (double)sq[c];
    __syncthreads();
    for (int o = CHUNK / 2; o > 0; o >>= 1) {
        if (c < o) red[c] += red[c + o];
        __syncthreads();
    }
    if (c == 0) g_chSq[cc] = red[0];
}

// ---------------- K6: Kogge-Stone scan of chunk sums (block per column) ----------------
__global__ void k_scan() {
    __shared__ double sh[NCHUNK];
    int b = blockIdx.x;   // [0,256)=P col, [256,512)=Q col, 512=chSp, 513=chSq
    int t = threadIdx.x;
    double val;
    if (b < DH)            val = g_chP[t * DH + b];
    else if (b < 2 * DH)   val = g_chQ[t * DH + (b - DH)];
    else if (b == 2 * DH)  val = g_chSp[t];
    else                   val = g_chSq[t];
    sh[t] = val;
    __syncthreads();
#pragma unroll
    for (int off = 1; off < NCHUNK; off <<= 1) {
        double x = (t >= off) ? sh[t - off] : 0.0;
        __syncthreads();
        sh[t] += x;
        __syncthreads();
    }
    double excl = (t == 0) ? 0.0 : sh[t - 1];
    if (b < DH) {
        g_chP[t * DH + b] = excl;
        if (t == 0) g_TotP[b] = sh[NCHUNK - 1];
    } else if (b < 2 * DH) {
        g_chQ[t * DH + (b - DH)] = excl;
    } else if (b == 2 * DH) {
        g_chSp[t] = excl;
        if (t == 0) g_SpTot = sh[NCHUNK - 1];
    } else {
        g_chSq[t] = excl;
    }
}

// ---------------- K7: fp32 suffix/prefix arrays (fp32 local accum off fp64 bases) ----------------
__global__ void k_prefix() {
    int cc = blockIdx.x;
    int c = threadIdx.x;
    __shared__ int   sperm[CHUNK];
    __shared__ float sp[CHUNK], sq[CHUNK];
    __shared__ double eP[CHUNK + 1], eQ[CHUNK + 1], ks[CHUNK];
    if (c < CHUNK) {
        int m = cc * CHUNK + c;
        sperm[c] = g_perm[m];
        sp[c] = g_ps[m];
        sq[c] = g_qs[m];
    }
    __syncthreads();
    if (c < CHUNK) ks[c] = (double)sp[c];
    __syncthreads();
#pragma unroll
    for (int o = 1; o < CHUNK; o <<= 1) {
        double x = (c < CHUNK && c >= o) ? ks[c - o] : 0.0;
        __syncthreads();
        if (c < CHUNK) ks[c] += x;
        __syncthreads();
    }
    if (c < CHUNK) { eP[c + 1] = ks[c]; if (c == 0) eP[0] = 0.0; }
    __syncthreads();
    if (c < CHUNK) ks[c] = (double)sq[c];
    __syncthreads();
#pragma unroll
    for (int o = 1; o < CHUNK; o <<= 1) {
        double x = (c < CHUNK && c >= o) ? ks[c - o] : 0.0;
        __syncthreads();
        if (c < CHUNK) ks[c] += x;
        __syncthreads();
    }
    if (c < CHUNK) { eQ[c + 1] = ks[c]; if (c == 0) eQ[0] = 0.0; }
    __syncthreads();

    double rp0 = g_chP[cc * DH + c];
    double rq0 = g_chQ[cc * DH + c];
    float sufBase = (float)(g_TotP[c] - rp0);
    float preBase = (float)rq0;
    float lp = 0.f, lq = 0.f;
#pragma unroll 4
    for (int u = 0; u < CHUNK; u++) {
        size_t m = (size_t)cc * CHUNK + u;
        g_SufP[m * DH + c] = sufBase - lp;
        g_PreQ[m * DH + c] = preBase + lq;
        float hv = g_h[(size_t)sperm[u] * DH + c];
        lp += sp[u] * hv;
        lq += sq[u] * hv;
    }
    if (cc == NCHUNK - 1) {
        g_SufP[(size_t)NROW * DH + c] = sufBase - lp;
        g_PreQ[(size_t)NROW * DH + c] = preBase + lq;
    }
    if (c < CHUNK) {
        int m = cc * CHUNK + c;
        double bSp = g_chSp[cc], bSq = g_chSq[cc], stot = g_SpTot;
        g_SpSuf[m] = stot - (bSp + eP[c]);
        g_SqPre[m] = bSq + eQ[c];
        if (cc == NCHUNK - 1 && c == CHUNK - 1) {
            g_SpSuf[NROW] = stot - (bSp + eP[CHUNK]);
            g_SqPre[NROW] = bSq + eQ[CHUNK];
        }
    }
}

// ---------------- K8: per-row coefficients (1 thread per row, fully parallel) ----------------
__global__ void k_coef(const float* __restrict__ a_b) {
    int i = blockIdx.x * 256 + threadIdx.x;
    float cb = __ldg(&a_b[0]);
    float s1 = g_s1[i];
    float s2m = ord2f(g_s2max_u);
    float u = s1 + cb + s2m;
    float m = u > 0.f ? u : SLOPE * u;              // exact row max of f(x)
    float alpha = expf(u - m);
    float beta  = expf(SLOPE * u - m);
    float t = -(s1 + cb);                           // x>0  <=>  s2[j] > t
    int lo = 0, hi = NROW;
    while (lo < hi) {
        int mid = (lo + hi) >> 1;
        if (g_s2s[mid] > t) hi = mid; else lo = mid + 1;
    }
    int k = lo;
    double Z = (double)alpha * g_SpSuf[k] + (double)beta * g_SqPre[k];
    g_rowA[i] = (float)((double)alpha / Z);
    g_rowB[i] = (float)((double)beta / Z);
    g_rowT[i] = t;
    g_rowK[i] = k;
}

// ---------------- K9: att (268 MB stream) + fused out gather on jx==0 blocks ----------------
__global__ void k_att(float* __restrict__ att, float* __restrict__ out) {
    int jx = blockIdx.x, iy = blockIdx.y;
    int i0 = iy * 32;
    if (jx == 0) {
        int c = threadIdx.x;
#pragma unroll 4
        for (int r = 0; r < 32; r++) {
            int i = i0 + r;
            float A = __ldg(&g_rowA[i]);
            float B = __ldg(&g_rowB[i]);
            int k = __ldg(&g_rowK[i]);
            float v = A * g_SufP[(size_t)k * DH + c] + B * g_PreQ[(size_t)k * DH + c];
            out[(size_t)i * DH + c] = v > 0.f ? v : SLOPE * v;
        }
    }
    int j = jx * 1024 + threadIdx.x * 4;
    float4 p = *(const float4*)&g_pj[j];
    float4 q = *(const float4*)&g_qj[j];
    float4 s = *(const float4*)&g_s2[j];
#pragma unroll 4
    for (int r = 0; r < 32; r++) {
        int i = i0 + r;
        float A = __ldg(&g_rowA[i]);
        float B = __ldg(&g_rowB[i]);
        float T = __ldg(&g_rowT[i]);
        float4 o;
        o.x = s.x > T ? A * p.x : B * q.x;
        o.y = s.y > T ? A * p.y : B * q.y;
        o.z = s.z > T ? A * p.z : B * q.z;
        o.w = s.w > T ? A * p.w : B * q.w;
        __stcs((float4*)&att[(size_t)i * NROW + j], o);
    }
}

// ---------------- launch ----------------
extern "C" void kernel_launch(void* const* d_in, const int* in_sizes, int n_in,
                              void* d_out, int out_size) {
    const float* doc = (const float*)d_in[0];
    const float* W   = (const float*)d_in[1];
    const float* Wb  = (const float*)d_in[2];
    const float* a   = (const float*)d_in[3];
    const float* ab  = (const float*)d_in[4];
    float* out = (float*)d_out;                  // [8192 x 256]
    float* att = out + (size_t)NROW * DH;        // [8192 x 8192]

    k_gemm<<<dim3(NROW / 128, DH / 64), 256>>>(doc, W, Wb);
    k_s<<<NROW / 8, 256>>>(a);
    k_rank_part<<<dim3(32, 8), 256>>>();
    k_scatter<<<32, 256>>>();
    k_chunk<<<NCHUNK, 256>>>();
    k_scan<<<2 * DH + 2, NCHUNK>>>();
    k_prefix<<<NCHUNK, 256>>>();
    k_coef<<<NROW / 256, 256>>>(ab);
    k_att<<<dim3(NROW / 1024, NROW / 32), 256>>>(att, out);
}

// round 7
// speedup vs baseline: 1.7850x; 1.0008x over previous
#include <cuda_runtime.h>
#include <math.h>

#define NROW 8192
#define DIN  512
#define DH   256
#define SLOPE 0.1f
#define CHUNK 64
#define NCHUNK 128   // NROW / CHUNK

// ---------------- scratch (device globals: no allocation allowed) ----------------
__device__ float    g_h[NROW * DH];                 // 8 MB
__device__ float    g_s1[NROW], g_s2[NROW];
__device__ unsigned g_s2max_u;
__device__ int      g_rank[NROW];
__device__ int      g_done[NROW];
__device__ float    g_pj[NROW], g_qj[NROW];         // original order
__device__ float    g_s2s[NROW];                    // sorted s2
__device__ int      g_perm[NROW];                   // sorted -> original
__device__ float    g_ps[NROW], g_qs[NROW];         // sorted order
__device__ double   g_chP[NCHUNK * DH], g_chQ[NCHUNK * DH];
__device__ double   g_chSp[NCHUNK], g_chSq[NCHUNK];
__device__ double   g_TotP[DH];
__device__ double   g_SpTot;
__device__ float    g_SufP[(NROW + 1) * DH];        // fp32 suffix of p*h (sorted)
__device__ float    g_PreQ[(NROW + 1) * DH];        // fp32 prefix of q*h (sorted)
__device__ double   g_SpSuf[NROW + 1], g_SqPre[NROW + 1];

// ordered-uint encoding of float for atomicMax
__device__ __forceinline__ unsigned f2ord(float x) {
    unsigned u = __float_as_uint(x);
    return (u & 0x80000000u) ? ~u : (u | 0x80000000u);
}
__device__ __forceinline__ float ord2f(unsigned u) {
    unsigned b = (u & 0x80000000u) ? (u & 0x7FFFFFFFu) : ~u;
    return __uint_as_float(b);
}

// packed f32x2 helpers (sm_100a: fma.rn.f32x2 — ptxas never emits it, PTX only)
__device__ __forceinline__ unsigned long long pack2(float v) {
    unsigned long long r;
    asm("mov.b64 %0, {%1, %1};" : "=l"(r) : "r"(__float_as_uint(v)));
    return r;
}
__device__ __forceinline__ unsigned long long fma2(unsigned long long a,
                                                   unsigned long long b,
                                                   unsigned long long c) {
    unsigned long long d;
    asm("fma.rn.f32x2 %0, %1, %2, %3;" : "=l"(d) : "l"(a), "l"(b), "l"(c));
    return d;
}
__device__ __forceinline__ void unpack2(unsigned long long v, float& lo, float& hi) {
    unsigned a, b;
    asm("mov.b64 {%0, %1}, %2;" : "=r"(a), "=r"(b) : "l"(v));
    lo = __uint_as_float(a); hi = __uint_as_float(b);
}

// ---------------- K1: h = doc @ W + W_b (fp32x2 SGEMM 128x64, double-buffered) ----------------
__global__ __launch_bounds__(256, 2) void k_gemm(const float* __restrict__ doc,
                                                 const float* __restrict__ W,
                                                 const float* __restrict__ Wb) {
    if (blockIdx.x == 0 && blockIdx.y == 0 && threadIdx.x == 0)
        g_s2max_u = 0u;   // reset ordered-max accumulator every replay
    __shared__ float As[2][16][128];   // [buf][k][m]
    __shared__ float Bs[2][16][64];    // [buf][k][n]
    const int bm = blockIdx.x * 128;
    const int bn = blockIdx.y * 64;
    const int tid = threadIdx.x;
    const int tr = tid >> 4, tc = tid & 15;   // thread tile 8m x 4n
    const int ar0 = tid >> 2,          ac0 = (tid & 3) << 2;
    const int ar1 = (tid + 256) >> 2,  ac1 = ((tid + 256) & 3) << 2;
    const int br  = tid >> 4,          bc  = (tid & 15) << 2;

    unsigned long long acc[4][4];
#pragma unroll
    for (int i = 0; i < 4; i++)
#pragma unroll
        for (int j = 0; j < 4; j++) acc[i][j] = 0ull;

    {
        float4 v0 = *(const float4*)&doc[(size_t)(bm + ar0) * DIN + ac0];
        float4 v1 = *(const float4*)&doc[(size_t)(bm + ar1) * DIN + ac1];
        float4 w  = *(const float4*)&W[(size_t)br * DH + bn + bc];
        As[0][ac0 + 0][ar0] = v0.x; As[0][ac0 + 1][ar0] = v0.y;
        As[0][ac0 + 2][ar0] = v0.z; As[0][ac0 + 3][ar0] = v0.w;
        As[0][ac1 + 0][ar1] = v1.x; As[0][ac1 + 1][ar1] = v1.y;
        As[0][ac1 + 2][ar1] = v1.z; As[0][ac1 + 3][ar1] = v1.w;
        *(float4*)&Bs[0][br][bc] = w;
    }
    __syncthreads();

    const int NSTEP = DIN / 16;   // 32
    for (int step = 0; step < NSTEP; step++) {
        int cur = step & 1;
        float4 v0, v1, w;
        if (step < NSTEP - 1) {
            int k0n = (step + 1) * 16;
            v0 = *(const float4*)&doc[(size_t)(bm + ar0) * DIN + k0n + ac0];
            v1 = *(const float4*)&doc[(size_t)(bm + ar1) * DIN + k0n + ac1];
            w  = *(const float4*)&W[(size_t)(k0n + br) * DH + bn + bc];
        }
#pragma unroll
        for (int kk = 0; kk < 16; kk++) {
            ulonglong2 av0 = *(const ulonglong2*)&As[cur][kk][tr * 8];
            ulonglong2 av1 = *(const ulonglong2*)&As[cur][kk][tr * 8 + 4];
            unsigned long long a64[4] = {av0.x, av0.y, av1.x, av1.y};
            float4 bf = *(const float4*)&Bs[cur][kk][tc * 4];
            unsigned long long bp[4] = {pack2(bf.x), pack2(bf.y), pack2(bf.z), pack2(bf.w)};
#pragma unroll
            for (int mp = 0; mp < 4; mp++)
#pragma unroll
                for (int n = 0; n < 4; n++)
                    acc[mp][n] = fma2(a64[mp], bp[n], acc[mp][n]);
        }
        if (step < NSTEP - 1) {
            int nxt = cur ^ 1;
            As[nxt][ac0 + 0][ar0] = v0.x; As[nxt][ac0 + 1][ar0] = v0.y;
            As[nxt][ac0 + 2][ar0] = v0.z; As[nxt][ac0 + 3][ar0] = v0.w;
            As[nxt][ac1 + 0][ar1] = v1.x; As[nxt][ac1 + 1][ar1] = v1.y;
            As[nxt][ac1 + 2][ar1] = v1.z; As[nxt][ac1 + 3][ar1] = v1.w;
            *(float4*)&Bs[nxt][br][bc] = w;
        }
        __syncthreads();
    }

    float4 wb = *(const float4*)&Wb[bn + tc * 4];
#pragma unroll
    for (int mp = 0; mp < 4; mp++) {
        int m0 = bm + tr * 8 + 2 * mp;
        float lo0, hi0, lo1, hi1, lo2, hi2, lo3, hi3;
        unpack2(acc[mp][0], lo0, hi0);
        unpack2(acc[mp][1], lo1, hi1);
        unpack2(acc[mp][2], lo2, hi2);
        unpack2(acc[mp][3], lo3, hi3);
        float4 r0, r1;
        r0.x = lo0 + wb.x; r0.y = lo1 + wb.y; r0.z = lo2 + wb.z; r0.w = lo3 + wb.w;
        r1.x = hi0 + wb.x; r1.y = hi1 + wb.y; r1.z = hi2 + wb.z; r1.w = hi3 + wb.w;
        *(float4*)&g_h[(size_t)m0 * DH + bn + tc * 4] = r0;
        *(float4*)&g_h[(size_t)(m0 + 1) * DH + bn + tc * 4] = r1;
    }
}

// ---------------- K2: s1 = h@a1, s2 = h@a2 (warp/row) + global max + counters zero ----------------
__global__ void k_s(const float* __restrict__ a) {
    __shared__ float smax[8];
    int wid = threadIdx.x >> 5;
    int lane = threadIdx.x & 31;
    int row = blockIdx.x * 8 + wid;
    const float* hr = &g_h[(size_t)row * DH];
    float s1 = 0.f, s2 = 0.f;
#pragma unroll
    for (int u = 0; u < 8; u++) {
        int c = u * 32 + lane;
        float hv = hr[c];
        s1 += hv * __ldg(&a[c]);
        s2 += hv * __ldg(&a[c + DH]);
    }
#pragma unroll
    for (int o = 16; o > 0; o >>= 1) {
        s1 += __shfl_xor_sync(0xffffffffu, s1, o);
        s2 += __shfl_xor_sync(0xffffffffu, s2, o);
    }
    if (lane == 0) {
        g_s1[row] = s1; g_s2[row] = s2;
        g_rank[row] = 0; g_done[row] = 0;
        smax[wid] = s2;
    }
    __syncthreads();
    if (threadIdx.x == 0) {
        float m = smax[0];
#pragma unroll
        for (int u = 1; u < 8; u++) m = fmaxf(m, smax[u]);
        atomicMax(&g_s2max_u, f2ord(m));
    }
}

// ---------------- K3: fused rank + scatter (last-arriver does the scatter) ----------------
__global__ void k_ranksc() {
    __shared__ float tile[256];
    int j = blockIdx.x * 256 + threadIdx.x;
    float v = g_s2[j];
    int base = blockIdx.y * 1024;
    int rank = 0;
    for (int t0 = base; t0 < base + 1024; t0 += 256) {
        tile[threadIdx.x] = g_s2[t0 + threadIdx.x];
        __syncthreads();
#pragma unroll 8
        for (int u = 0; u < 256; u++) {
            float w = tile[u];
            rank += (int)((w < v) || (w == v && (t0 + u) < j));
        }
        __syncthreads();
    }
    atomicAdd(&g_rank[j], rank);
    __threadfence();
    int old = atomicAdd(&g_done[j], 1);
    if (old == 7) {                       // all 8 partials in: this thread scatters j
        __threadfence();
        int r = *(volatile int*)&g_rank[j];
        float s2m = ord2f(g_s2max_u);
        float p = expf(v - s2m);
        float q = expf(SLOPE * (v - s2m));
        g_pj[j] = p; g_qj[j] = q;
        g_s2s[r] = v; g_perm[r] = j;
        g_ps[r] = p;  g_qs[r] = q;
    }
}

// ---------------- K4: per-chunk sums of p*h, q*h (fp32 accum, fp64 store) ----------------
__global__ void k_chunk() {
    int cc = blockIdx.x;
    int c = threadIdx.x;
    __shared__ int   sperm[CHUNK];
    __shared__ float sp[CHUNK], sq[CHUNK];
    __shared__ double red[CHUNK];
    if (c < CHUNK) {
        int m = cc * CHUNK + c;
        sperm[c] = g_perm[m];
        sp[c] = g_ps[m];
        sq[c] = g_qs[m];
    }
    __syncthreads();
    float ap0 = 0.f, ap1 = 0.f, aq0 = 0.f, aq1 = 0.f;
#pragma unroll 4
    for (int u = 0; u < CHUNK; u += 2) {
        float h0 = g_h[(size_t)sperm[u] * DH + c];
        float h1 = g_h[(size_t)sperm[u + 1] * DH + c];
        ap0 += sp[u] * h0;     aq0 += sq[u] * h0;
        ap1 += sp[u + 1] * h1; aq1 += sq[u + 1] * h1;
    }
    g_chP[cc * DH + c] = (double)(ap0 + ap1);
    g_chQ[cc * DH + c] = (double)(aq0 + aq1);
    if (c < CHUNK) red[c] = (double)sp[c];
    __syncthreads();
    for (int o = CHUNK / 2; o > 0; o >>= 1) {
        if (c < o) red[c] += red[c + o];
        __syncthreads();
    }
    if (c == 0) g_chSp[cc] = red[0];
    __syncthreads();
    if (c < CHUNK) red[c] = (double)sq[c];
    __syncthreads();
    for (int o = CHUNK / 2; o > 0; o >>= 1) {
        if (c < o) red[c] += red[c + o];
        __syncthreads();
    }
    if (c == 0) g_chSq[cc] = red[0];
}

// ---------------- K5: Kogge-Stone scan of chunk sums (block per column) ----------------
__global__ void k_scan() {
    __shared__ double sh[NCHUNK];
    int b = blockIdx.x;   // [0,256)=P col, [256,512)=Q col, 512=chSp, 513=chSq
    int t = threadIdx.x;
    double val;
    if (b < DH)            val = g_chP[t * DH + b];
    else if (b < 2 * DH)   val = g_chQ[t * DH + (b - DH)];
    else if (b == 2 * DH)  val = g_chSp[t];
    else                   val = g_chSq[t];
    sh[t] = val;
    __syncthreads();
#pragma unroll
    for (int off = 1; off < NCHUNK; off <<= 1) {
        double x = (t >= off) ? sh[t - off] : 0.0;
        __syncthreads();
        sh[t] += x;
        __syncthreads();
    }
    double excl = (t == 0) ? 0.0 : sh[t - 1];
    if (b < DH) {
        g_chP[t * DH + b] = excl;
        if (t == 0) g_TotP[b] = sh[NCHUNK - 1];
    } else if (b < 2 * DH) {
        g_chQ[t * DH + (b - DH)] = excl;
    } else if (b == 2 * DH) {
        g_chSp[t] = excl;
        if (t == 0) g_SpTot = sh[NCHUNK - 1];
    } else {
        g_chSq[t] = excl;
    }
}

// ---------------- K6: fp32 suffix/prefix arrays (fp32 local accum off fp64 bases) ----------------
__global__ void k_prefix() {
    int cc = blockIdx.x;
    int c = threadIdx.x;
    __shared__ int   sperm[CHUNK];
    __shared__ float sp[CHUNK], sq[CHUNK];
    __shared__ double eP[CHUNK + 1], eQ[CHUNK + 1], ks[CHUNK];
    if (c < CHUNK) {
        int m = cc * CHUNK + c;
        sperm[c] = g_perm[m];
        sp[c] = g_ps[m];
        sq[c] = g_qs[m];
    }
    __syncthreads();
    if (c < CHUNK) ks[c] = (double)sp[c];
    __syncthreads();
#pragma unroll
    for (int o = 1; o < CHUNK; o <<= 1) {
        double x = (c < CHUNK && c >= o) ? ks[c - o] : 0.0;
        __syncthreads();
        if (c < CHUNK) ks[c] += x;
        __syncthreads();
    }
    if (c < CHUNK) { eP[c + 1] = ks[c]; if (c == 0) eP[0] = 0.0; }
    __syncthreads();
    if (c < CHUNK) ks[c] = (double)sq[c];
    __syncthreads();
#pragma unroll
    for (int o = 1; o < CHUNK; o <<= 1) {
        double x = (c < CHUNK && c >= o) ? ks[c - o] : 0.0;
        __syncthreads();
        if (c < CHUNK) ks[c] += x;
        __syncthreads();
    }
    if (c < CHUNK) { eQ[c + 1] = ks[c]; if (c == 0) eQ[0] = 0.0; }
    __syncthreads();

    double rp0 = g_chP[cc * DH + c];
    double rq0 = g_chQ[cc * DH + c];
    float sufBase = (float)(g_TotP[c] - rp0);
    float preBase = (float)rq0;
    float lp = 0.f, lq = 0.f;
#pragma unroll 4
    for (int u = 0; u < CHUNK; u++) {
        size_t m = (size_t)cc * CHUNK + u;
        g_SufP[m * DH + c] = sufBase - lp;
        g_PreQ[m * DH + c] = preBase + lq;
        float hv = g_h[(size_t)sperm[u] * DH + c];
        lp += sp[u] * hv;
        lq += sq[u] * hv;
    }
    if (cc == NCHUNK - 1) {
        g_SufP[(size_t)NROW * DH + c] = sufBase - lp;
        g_PreQ[(size_t)NROW * DH + c] = preBase + lq;
    }
    if (c < CHUNK) {
        int m = cc * CHUNK + c;
        double bSp = g_chSp[cc], bSq = g_chSq[cc], stot = g_SpTot;
        g_SpSuf[m] = stot - (bSp + eP[c]);
        g_SqPre[m] = bSq + eQ[c];
        if (cc == NCHUNK - 1 && c == CHUNK - 1) {
            g_SpSuf[NROW] = stot - (bSp + eP[CHUNK]);
            g_SqPre[NROW] = bSq + eQ[CHUNK];
        }
    }
}

// ---------------- K7: att (268 MB stream) + per-block coefs + fused out gather ----------------
__global__ void k_att(float* __restrict__ att, float* __restrict__ out,
                      const float* __restrict__ a_b) {
    __shared__ float sA[32], sB[32], sT[32];
    __shared__ int   sK[32];
    int jx = blockIdx.x, iy = blockIdx.y;
    int i0 = iy * 32;
    int tid = threadIdx.x;
    if (tid < 32) {
        int i = i0 + tid;
        float cb = __ldg(&a_b[0]);
        float s1 = g_s1[i];
        float s2m = ord2f(g_s2max_u);
        float u = s1 + cb + s2m;
        float m = u > 0.f ? u : SLOPE * u;          // exact row max of f(x)
        float alpha = expf(u - m);
        float beta  = expf(SLOPE * u - m);
        float t = -(s1 + cb);                       // x>0  <=>  s2[j] > t
        int lo = 0, hi = NROW;
        while (lo < hi) {
            int mid = (lo + hi) >> 1;
            if (g_s2s[mid] > t) hi = mid; else lo = mid + 1;
        }
        int k = lo;
        double Z = (double)alpha * g_SpSuf[k] + (double)beta * g_SqPre[k];
        float Zf = (float)Z;
        sA[tid] = alpha / Zf;
        sB[tid] = beta / Zf;
        sT[tid] = t;
        sK[tid] = k;
    }
    __syncthreads();
    if (jx == 0) {
        int c = tid;
#pragma unroll 4
        for (int r = 0; r < 32; r++) {
            int i = i0 + r;
            int k = sK[r];
            float v = sA[r] * g_SufP[(size_t)k * DH + c] + sB[r] * g_PreQ[(size_t)k * DH + c];
            out[(size_t)i * DH + c] = v > 0.f ? v : SLOPE * v;
        }
    }
    int j = jx * 1024 + tid * 4;
    float4 p = *(const float4*)&g_pj[j];
    float4 q = *(const float4*)&g_qj[j];
    float4 s = *(const float4*)&g_s2[j];
#pragma unroll 4
    for (int r = 0; r < 32; r++) {
        int i = i0 + r;
        float A = sA[r];
        float B = sB[r];
        float T = sT[r];
        float4 o;
        o.x = s.x > T ? A * p.x : B * q.x;
        o.y = s.y > T ? A * p.y : B * q.y;
        o.z = s.z > T ? A * p.z : B * q.z;
        o.w = s.w > T ? A * p.w : B * q.w;
        __stcs((float4*)&att[(size_t)i * NROW + j], o);
    }
}

// ---------------- launch ----------------
extern "C" void kernel_launch(void* const* d_in, const int* in_sizes, int n_in,
                              void* d_out, int out_size) {
    const float* doc = (const float*)d_in[0];
    const float* W   = (const float*)d_in[1];
    const float* Wb  = (const float*)d_in[2];
    const float* a   = (const float*)d_in[3];
    const float* ab  = (const float*)d_in[4];
    float* out = (float*)d_out;                  // [8192 x 256]
    float* att = out + (size_t)NROW * DH;        // [8192 x 8192]

    k_gemm<<<dim3(NROW / 128, DH / 64), 256>>>(doc, W, Wb);
    k_s<<<NROW / 8, 256>>>(a);
    k_ranksc<<<dim3(32, 8), 256>>>();
    k_chunk<<<NCHUNK, 256>>>();
    k_scan<<<2 * DH + 2, NCHUNK>>>();
    k_prefix<<<NCHUNK, 256>>>();
    k_att<<<dim3(NROW / 1024, NROW / 32), 256>>>(att, out, ab);
}

// round 8
// speedup vs baseline: 1.8592x; 1.0416x over previous
#include <cuda_runtime.h>
#include <math.h>

#define NROW 8192
#define DIN  512
#define DH   256
#define SLOPE 0.1f
#define CHUNK 16
#define NCHUNK 512   // NROW / CHUNK

// ---------------- scratch (device globals: no allocation allowed) ----------------
__device__ float    g_h[NROW * DH];                 // 8 MB
__device__ float    g_s1[NROW], g_s2[NROW];
__device__ unsigned g_s2max_u;
__device__ int      g_rank[NROW];
__device__ int      g_done[NROW];
__device__ float    g_pj[NROW], g_qj[NROW];         // original order
__device__ float    g_s2s[NROW];                    // sorted s2
__device__ int      g_perm[NROW];                   // sorted -> original
__device__ float    g_ps[NROW], g_qs[NROW];         // sorted order
__device__ double   g_chP[NCHUNK * DH], g_chQ[NCHUNK * DH];   // 1 MB each
__device__ double   g_chSp[NCHUNK], g_chSq[NCHUNK];
__device__ double   g_TotP[DH];
__device__ double   g_SpTot;
__device__ float    g_SufP[(NROW + 1) * DH];        // fp32 suffix of p*h (sorted)
__device__ float    g_PreQ[(NROW + 1) * DH];        // fp32 prefix of q*h (sorted)
__device__ double   g_SpSuf[NROW + 1], g_SqPre[NROW + 1];

// ordered-uint encoding of float for atomicMax
__device__ __forceinline__ unsigned f2ord(float x) {
    unsigned u = __float_as_uint(x);
    return (u & 0x80000000u) ? ~u : (u | 0x80000000u);
}
__device__ __forceinline__ float ord2f(unsigned u) {
    unsigned b = (u & 0x80000000u) ? (u & 0x7FFFFFFFu) : ~u;
    return __uint_as_float(b);
}

// packed f32x2 helpers (sm_100a: fma.rn.f32x2 — ptxas never emits it, PTX only)
__device__ __forceinline__ unsigned long long pack2(float v) {
    unsigned long long r;
    asm("mov.b64 %0, {%1, %1};" : "=l"(r) : "r"(__float_as_uint(v)));
    return r;
}
__device__ __forceinline__ unsigned long long fma2(unsigned long long a,
                                                   unsigned long long b,
                                                   unsigned long long c) {
    unsigned long long d;
    asm("fma.rn.f32x2 %0, %1, %2, %3;" : "=l"(d) : "l"(a), "l"(b), "l"(c));
    return d;
}
__device__ __forceinline__ void unpack2(unsigned long long v, float& lo, float& hi) {
    unsigned a, b;
    asm("mov.b64 {%0, %1}, %2;" : "=r"(a), "=r"(b) : "l"(v));
    lo = __uint_as_float(a); hi = __uint_as_float(b);
}

// ---------------- K1: h = doc @ W + W_b (fp32x2 SGEMM 128x64, double-buffered) ----------------
__global__ __launch_bounds__(256, 2) void k_gemm(const float* __restrict__ doc,
                                                 const float* __restrict__ W,
                                                 const float* __restrict__ Wb) {
    if (blockIdx.x == 0 && blockIdx.y == 0 && threadIdx.x == 0)
        g_s2max_u = 0u;   // reset ordered-max accumulator every replay
    __shared__ float As[2][16][128];   // [buf][k][m]
    __shared__ float Bs[2][16][64];    // [buf][k][n]
    const int bm = blockIdx.x * 128;
    const int bn = blockIdx.y * 64;
    const int tid = threadIdx.x;
    const int tr = tid >> 4, tc = tid & 15;   // thread tile 8m x 4n
    const int ar0 = tid >> 2,          ac0 = (tid & 3) << 2;
    const int ar1 = (tid + 256) >> 2,  ac1 = ((tid + 256) & 3) << 2;
    const int br  = tid >> 4,          bc  = (tid & 15) << 2;

    unsigned long long acc[4][4];
#pragma unroll
    for (int i = 0; i < 4; i++)
#pragma unroll
        for (int j = 0; j < 4; j++) acc[i][j] = 0ull;

    {
        float4 v0 = *(const float4*)&doc[(size_t)(bm + ar0) * DIN + ac0];
        float4 v1 = *(const float4*)&doc[(size_t)(bm + ar1) * DIN + ac1];
        float4 w  = *(const float4*)&W[(size_t)br * DH + bn + bc];
        As[0][ac0 + 0][ar0] = v0.x; As[0][ac0 + 1][ar0] = v0.y;
        As[0][ac0 + 2][ar0] = v0.z; As[0][ac0 + 3][ar0] = v0.w;
        As[0][ac1 + 0][ar1] = v1.x; As[0][ac1 + 1][ar1] = v1.y;
        As[0][ac1 + 2][ar1] = v1.z; As[0][ac1 + 3][ar1] = v1.w;
        *(float4*)&Bs[0][br][bc] = w;
    }
    __syncthreads();

    const int NSTEP = DIN / 16;   // 32
    for (int step = 0; step < NSTEP; step++) {
        int cur = step & 1;
        float4 v0, v1, w;
        if (step < NSTEP - 1) {
            int k0n = (step + 1) * 16;
            v0 = *(const float4*)&doc[(size_t)(bm + ar0) * DIN + k0n + ac0];
            v1 = *(const float4*)&doc[(size_t)(bm + ar1) * DIN + k0n + ac1];
            w  = *(const float4*)&W[(size_t)(k0n + br) * DH + bn + bc];
        }
#pragma unroll
        for (int kk = 0; kk < 16; kk++) {
            ulonglong2 av0 = *(const ulonglong2*)&As[cur][kk][tr * 8];
            ulonglong2 av1 = *(const ulonglong2*)&As[cur][kk][tr * 8 + 4];
            unsigned long long a64[4] = {av0.x, av0.y, av1.x, av1.y};
            float4 bf = *(const float4*)&Bs[cur][kk][tc * 4];
            unsigned long long bp[4] = {pack2(bf.x), pack2(bf.y), pack2(bf.z), pack2(bf.w)};
#pragma unroll
            for (int mp = 0; mp < 4; mp++)
#pragma unroll
                for (int n = 0; n < 4; n++)
                    acc[mp][n] = fma2(a64[mp], bp[n], acc[mp][n]);
        }
        if (step < NSTEP - 1) {
            int nxt = cur ^ 1;
            As[nxt][ac0 + 0][ar0] = v0.x; As[nxt][ac0 + 1][ar0] = v0.y;
            As[nxt][ac0 + 2][ar0] = v0.z; As[nxt][ac0 + 3][ar0] = v0.w;
            As[nxt][ac1 + 0][ar1] = v1.x; As[nxt][ac1 + 1][ar1] = v1.y;
            As[nxt][ac1 + 2][ar1] = v1.z; As[nxt][ac1 + 3][ar1] = v1.w;
            *(float4*)&Bs[nxt][br][bc] = w;
        }
        __syncthreads();
    }

    float4 wb = *(const float4*)&Wb[bn + tc * 4];
#pragma unroll
    for (int mp = 0; mp < 4; mp++) {
        int m0 = bm + tr * 8 + 2 * mp;
        float lo0, hi0, lo1, hi1, lo2, hi2, lo3, hi3;
        unpack2(acc[mp][0], lo0, hi0);
        unpack2(acc[mp][1], lo1, hi1);
        unpack2(acc[mp][2], lo2, hi2);
        unpack2(acc[mp][3], lo3, hi3);
        float4 r0, r1;
        r0.x = lo0 + wb.x; r0.y = lo1 + wb.y; r0.z = lo2 + wb.z; r0.w = lo3 + wb.w;
        r1.x = hi0 + wb.x; r1.y = hi1 + wb.y; r1.z = hi2 + wb.z; r1.w = hi3 + wb.w;
        *(float4*)&g_h[(size_t)m0 * DH + bn + tc * 4] = r0;
        *(float4*)&g_h[(size_t)(m0 + 1) * DH + bn + tc * 4] = r1;
    }
}

// ---------------- K2: s1 = h@a1, s2 = h@a2 (warp/row) + global max + counters zero ----------------
__global__ void k_s(const float* __restrict__ a) {
    __shared__ float smax[8];
    int wid = threadIdx.x >> 5;
    int lane = threadIdx.x & 31;
    int row = blockIdx.x * 8 + wid;
    const float* hr = &g_h[(size_t)row * DH];
    float s1 = 0.f, s2 = 0.f;
#pragma unroll
    for (int u = 0; u < 8; u++) {
        int c = u * 32 + lane;
        float hv = hr[c];
        s1 += hv * __ldg(&a[c]);
        s2 += hv * __ldg(&a[c + DH]);
    }
#pragma unroll
    for (int o = 16; o > 0; o >>= 1) {
        s1 += __shfl_xor_sync(0xffffffffu, s1, o);
        s2 += __shfl_xor_sync(0xffffffffu, s2, o);
    }
    if (lane == 0) {
        g_s1[row] = s1; g_s2[row] = s2;
        g_rank[row] = 0; g_done[row] = 0;
        smax[wid] = s2;
    }
    __syncthreads();
    if (threadIdx.x == 0) {
        float m = smax[0];
#pragma unroll
        for (int u = 1; u < 8; u++) m = fmaxf(m, smax[u]);
        atomicMax(&g_s2max_u, f2ord(m));
    }
}

// ---------------- K3: fused rank + scatter (last-arriver does the scatter) ----------------
__global__ void k_ranksc() {
    __shared__ float tile[256];
    int j = blockIdx.x * 256 + threadIdx.x;
    float v = g_s2[j];
    int base = blockIdx.y * 1024;
    int rank = 0;
    for (int t0 = base; t0 < base + 1024; t0 += 256) {
        tile[threadIdx.x] = g_s2[t0 + threadIdx.x];
        __syncthreads();
#pragma unroll 8
        for (int u = 0; u < 256; u++) {
            float w = tile[u];
            rank += (int)((w < v) || (w == v && (t0 + u) < j));
        }
        __syncthreads();
    }
    atomicAdd(&g_rank[j], rank);
    __threadfence();
    int old = atomicAdd(&g_done[j], 1);
    if (old == 7) {                       // all 8 partials in: this thread scatters j
        __threadfence();
        int r = *(volatile int*)&g_rank[j];
        float s2m = ord2f(g_s2max_u);
        float p = expf(v - s2m);
        float q = expf(SLOPE * (v - s2m));
        g_pj[j] = p; g_qj[j] = q;
        g_s2s[r] = v; g_perm[r] = j;
        g_ps[r] = p;  g_qs[r] = q;
    }
}

// ---------------- K4: per-chunk sums of p*h, q*h (CHUNK=16, 512 CTAs) ----------------
__global__ void k_chunk() {
    int cc = blockIdx.x;
    int c = threadIdx.x;
    __shared__ int   sperm[CHUNK];
    __shared__ float sp[CHUNK], sq[CHUNK];
    __shared__ double red[CHUNK];
    if (c < CHUNK) {
        int m = cc * CHUNK + c;
        sperm[c] = g_perm[m];
        sp[c] = g_ps[m];
        sq[c] = g_qs[m];
    }
    __syncthreads();
    float ap = 0.f, aq = 0.f;
#pragma unroll
    for (int u = 0; u < CHUNK; u++) {
        float hv = g_h[(size_t)sperm[u] * DH + c];
        ap += sp[u] * hv;
        aq += sq[u] * hv;
    }
    g_chP[(size_t)cc * DH + c] = (double)ap;
    g_chQ[(size_t)cc * DH + c] = (double)aq;
    if (c < CHUNK) red[c] = (double)sp[c];
    __syncthreads();
#pragma unroll
    for (int o = CHUNK / 2; o > 0; o >>= 1) {
        if (c < o) red[c] += red[c + o];
        __syncthreads();
    }
    if (c == 0) g_chSp[cc] = red[0];
    __syncthreads();
    if (c < CHUNK) red[c] = (double)sq[c];
    __syncthreads();
#pragma unroll
    for (int o = CHUNK / 2; o > 0; o >>= 1) {
        if (c < o) red[c] += red[c + o];
        __syncthreads();
    }
    if (c == 0) g_chSq[cc] = red[0];
}

// ---------------- K5: Kogge-Stone scan of chunk sums (block per column, 512-wide) ----------------
__global__ void k_scan() {
    __shared__ double sh[NCHUNK];
    int b = blockIdx.x;   // [0,256)=P col, [256,512)=Q col, 512=chSp, 513=chSq
    int t = threadIdx.x;
    double val;
    if (b < DH)            val = g_chP[(size_t)t * DH + b];
    else if (b < 2 * DH)   val = g_chQ[(size_t)t * DH + (b - DH)];
    else if (b == 2 * DH)  val = g_chSp[t];
    else                   val = g_chSq[t];
    sh[t] = val;
    __syncthreads();
#pragma unroll
    for (int off = 1; off < NCHUNK; off <<= 1) {
        double x = (t >= off) ? sh[t - off] : 0.0;
        __syncthreads();
        sh[t] += x;
        __syncthreads();
    }
    double excl = (t == 0) ? 0.0 : sh[t - 1];
    if (b < DH) {
        g_chP[(size_t)t * DH + b] = excl;
        if (t == 0) g_TotP[b] = sh[NCHUNK - 1];
    } else if (b < 2 * DH) {
        g_chQ[(size_t)t * DH + (b - DH)] = excl;
    } else if (b == 2 * DH) {
        g_chSp[t] = excl;
        if (t == 0) g_SpTot = sh[NCHUNK - 1];
    } else {
        g_chSq[t] = excl;
    }
}

// ---------------- K6: fp32 suffix/prefix arrays (CHUNK=16, 512 CTAs) ----------------
__global__ void k_prefix() {
    int cc = blockIdx.x;
    int c = threadIdx.x;
    __shared__ int   sperm[CHUNK];
    __shared__ float sp[CHUNK], sq[CHUNK];
    __shared__ double eP[CHUNK + 1], eQ[CHUNK + 1], ks[CHUNK];
    if (c < CHUNK) {
        int m = cc * CHUNK + c;
        sperm[c] = g_perm[m];
        sp[c] = g_ps[m];
        sq[c] = g_qs[m];
    }
    __syncthreads();
    if (c < CHUNK) ks[c] = (double)sp[c];
    __syncthreads();
#pragma unroll
    for (int o = 1; o < CHUNK; o <<= 1) {
        double x = (c < CHUNK && c >= o) ? ks[c - o] : 0.0;
        __syncthreads();
        if (c < CHUNK) ks[c] += x;
        __syncthreads();
    }
    if (c < CHUNK) { eP[c + 1] = ks[c]; if (c == 0) eP[0] = 0.0; }
    __syncthreads();
    if (c < CHUNK) ks[c] = (double)sq[c];
    __syncthreads();
#pragma unroll
    for (int o = 1; o < CHUNK; o <<= 1) {
        double x = (c < CHUNK && c >= o) ? ks[c - o] : 0.0;
        __syncthreads();
        if (c < CHUNK) ks[c] += x;
        __syncthreads();
    }
    if (c < CHUNK) { eQ[c + 1] = ks[c]; if (c == 0) eQ[0] = 0.0; }
    __syncthreads();

    double rp0 = g_chP[(size_t)cc * DH + c];
    double rq0 = g_chQ[(size_t)cc * DH + c];
    float sufBase = (float)(g_TotP[c] - rp0);
    float preBase = (float)rq0;
    float lp = 0.f, lq = 0.f;
#pragma unroll
    for (int u = 0; u < CHUNK; u++) {
        size_t m = (size_t)cc * CHUNK + u;
        g_SufP[m * DH + c] = sufBase - lp;
        g_PreQ[m * DH + c] = preBase + lq;
        float hv = g_h[(size_t)sperm[u] * DH + c];
        lp += sp[u] * hv;
        lq += sq[u] * hv;
    }
    if (cc == NCHUNK - 1) {
        g_SufP[(size_t)NROW * DH + c] = sufBase - lp;
        g_PreQ[(size_t)NROW * DH + c] = preBase + lq;
    }
    if (c < CHUNK) {
        int m = cc * CHUNK + c;
        double bSp = g_chSp[cc], bSq = g_chSq[cc], stot = g_SpTot;
        g_SpSuf[m] = stot - (bSp + eP[c]);
        g_SqPre[m] = bSq + eQ[c];
        if (cc == NCHUNK - 1 && c == CHUNK - 1) {
            g_SpSuf[NROW] = stot - (bSp + eP[CHUNK]);
            g_SqPre[NROW] = bSq + eQ[CHUNK];
        }
    }
}

// ---------------- K7: att (268 MB stream) + per-block coefs + fused out gather ----------------
__global__ void k_att(float* __restrict__ att, float* __restrict__ out,
                      const float* __restrict__ a_b) {
    __shared__ float sA[32], sB[32], sT[32];
    __shared__ int   sK[32];
    int jx = blockIdx.x, iy = blockIdx.y;
    int i0 = iy * 32;
    int tid = threadIdx.x;
    if (tid < 32) {
        int i = i0 + tid;
        float cb = __ldg(&a_b[0]);
        float s1 = g_s1[i];
        float s2m = ord2f(g_s2max_u);
        float u = s1 + cb + s2m;
        float m = u > 0.f ? u : SLOPE * u;          // exact row max of f(x)
        float alpha = expf(u - m);
        float beta  = expf(SLOPE * u - m);
        float t = -(s1 + cb);                       // x>0  <=>  s2[j] > t
        int lo = 0, hi = NROW;
        while (lo < hi) {
            int mid = (lo + hi) >> 1;
            if (g_s2s[mid] > t) hi = mid; else lo = mid + 1;
        }
        int k = lo;
        double Z = (double)alpha * g_SpSuf[k] + (double)beta * g_SqPre[k];
        float Zf = (float)Z;
        sA[tid] = alpha / Zf;
        sB[tid] = beta / Zf;
        sT[tid] = t;
        sK[tid] = k;
    }
    __syncthreads();
    if (jx == 0) {
        int c = tid;
#pragma unroll 4
        for (int r = 0; r < 32; r++) {
            int i = i0 + r;
            int k = sK[r];
            float v = sA[r] * g_SufP[(size_t)k * DH + c] + sB[r] * g_PreQ[(size_t)k * DH + c];
            out[(size_t)i * DH + c] = v > 0.f ? v : SLOPE * v;
        }
    }
    int j = jx * 1024 + tid * 4;
    float4 p = *(const float4*)&g_pj[j];
    float4 q = *(const float4*)&g_qj[j];
    float4 s = *(const float4*)&g_s2[j];
#pragma unroll 4
    for (int r = 0; r < 32; r++) {
        int i = i0 + r;
        float A = sA[r];
        float B = sB[r];
        float T = sT[r];
        float4 o;
        o.x = s.x > T ? A * p.x : B * q.x;
        o.y = s.y > T ? A * p.y : B * q.y;
        o.z = s.z > T ? A * p.z : B * q.z;
        o.w = s.w > T ? A * p.w : B * q.w;
        __stcs((float4*)&att[(size_t)i * NROW + j], o);
    }
}

// ---------------- launch ----------------
extern "C" void kernel_launch(void* const* d_in, const int* in_sizes, int n_in,
                              void* d_out, int out_size) {
    const float* doc = (const float*)d_in[0];
    const float* W   = (const float*)d_in[1];
    const float* Wb  = (const float*)d_in[2];
    const float* a   = (const float*)d_in[3];
    const float* ab  = (const float*)d_in[4];
    float* out = (float*)d_out;                  // [8192 x 256]
    float* att = out + (size_t)NROW * DH;        // [8192 x 8192]

    k_gemm<<<dim3(NROW / 128, DH / 64), 256>>>(doc, W, Wb);
    k_s<<<NROW / 8, 256>>>(a);
    k_ranksc<<<dim3(32, 8), 256>>>();
    k_chunk<<<NCHUNK, 256>>>();
    k_scan<<<2 * DH + 2, NCHUNK>>>();
    k_prefix<<<NCHUNK, 256>>>();
    k_att<<<dim3(NROW / 1024, NROW / 32), 256>>>(att, out, ab);
}